// round 11
// baseline (speedup 1.0000x reference)
#include <cuda_runtime.h>
#include <cuda_fp16.h>

#define T_STEPS 2048
#define BATCH   256
#define HID     64
#define EMBED   128
#define GATES   256

__device__ __forceinline__ float fast_tanh(float x) {
    float y;
    asm("tanh.approx.f32 %0, %1;" : "=f"(y) : "f"(x));
    return y;
}
__device__ __forceinline__ float fast_sigm(float x) {
    return fmaf(fast_tanh(0.5f * x), 0.5f, 0.5f);
}
__device__ __forceinline__ __half2 u2h2(unsigned int u) {
    return *reinterpret_cast<__half2*>(&u);
}

// Thread->gate map (per 256-thread group): warp w, lane l: unit j = w*8+(l>>2),
// type = l&3 (0:i 1:f 2:g 3:o), weight row gr = type*64+j. xor-shuffles deliver
// (i,f,g,o) to the type==0 lane which owns the c/h update. Non-type0 lanes
// compute bounded garbage; never committed.
//
// Warp specialization: 512 threads. Group A (tid<256) = layers 0+1, group B
// (tid>=256) = layer 2. Diagonal pipeline (l0[t=s], l1[t=s-1], l2[t=s-2]);
// all reads hit the previous superstep's parity array, so the layer partition
// needs only one block-wide bar.sync per superstep. Groups run different code
// -> their tails/dots interleave on each SMSP (2 A-warps + 2 B-warps).

#define BAR_ALL() asm volatile("bar.sync 0, 512;" ::: "memory")

// Per-layer tail: tree-reduce accs in fp32, nonlinearity, parallel xor-shuffles,
// c/h update, pack h as half2 into DST[LYR].
#define LSTM_TAIL(DST, LYR, ACC0, ACC1, IN0, IN1, Cr0, Cr1, H0OUT, H1OUT)      \
    {                                                                          \
        float2 sa_ = __half22float2(ACC0[0]), sb_ = __half22float2(ACC0[1]);   \
        float2 sc_ = __half22float2(ACC0[2]), sd_ = __half22float2(ACC0[3]);   \
        float v0 = (IN0) + (((sa_.x + sa_.y) + (sb_.x + sb_.y)) +              \
                            ((sc_.x + sc_.y) + (sd_.x + sd_.y)));              \
        sa_ = __half22float2(ACC1[0]); sb_ = __half22float2(ACC1[1]);          \
        sc_ = __half22float2(ACC1[2]); sd_ = __half22float2(ACC1[3]);          \
        float v1 = (IN1) + (((sa_.x + sa_.y) + (sb_.x + sb_.y)) +              \
                            ((sc_.x + sc_.y) + (sd_.x + sd_.y)));              \
        if (type == 2) { v0 = fast_tanh(v0); v1 = fast_tanh(v1); }             \
        else           { v0 = fast_sigm(v0); v1 = fast_sigm(v1); }             \
        float f0 = __shfl_xor_sync(0xffffffffu, v0, 1);                        \
        float g0 = __shfl_xor_sync(0xffffffffu, v0, 2);                        \
        float o0 = __shfl_xor_sync(0xffffffffu, v0, 3);                        \
        float f1 = __shfl_xor_sync(0xffffffffu, v1, 1);                        \
        float g1 = __shfl_xor_sync(0xffffffffu, v1, 2);                        \
        float o1 = __shfl_xor_sync(0xffffffffu, v1, 3);                        \
        Cr0 = f0 * Cr0 + v0 * g0;                                              \
        Cr1 = f1 * Cr1 + v1 * g1;                                              \
        float h0_ = o0 * fast_tanh(Cr0);                                       \
        float h1_ = o1 * fast_tanh(Cr1);                                       \
        float hn0_ = __shfl_down_sync(0xffffffffu, h0_, 4);                    \
        float hn1_ = __shfl_down_sync(0xffffffffu, h1_, 4);                    \
        if (type == 0 && (j & 1) == 0) {                                       \
            DST[LYR][0][j >> 1] = __floats2half2_rn(h0_, hn0_);                \
            DST[LYR][1][j >> 1] = __floats2half2_rn(h1_, hn1_);                \
        }                                                                      \
        H0OUT = h0_; H1OUT = h1_;                                              \
    }

// Group A superstep: l0 rec (weights from smem w0s) + l1 (w1i over h0, w1r over h1).
#define ASTEP(SRC, DST, SVAL)                                                  \
    {                                                                          \
        const int s_ = (SVAL);                                                 \
        __half2 A0[4], A1[4], B0[4], B1[4];                                    \
        _Pragma("unroll")                                                      \
        for (int i = 0; i < 4; i++) {                                          \
            A0[i] = __float2half2_rn(0.f); A1[i] = __float2half2_rn(0.f);      \
            B0[i] = __float2half2_rn(0.f); B1[i] = __float2half2_rn(0.f);      \
        }                                                                      \
        {   /* Phase 1: h0 -> l0 rec (A, smem weights) + l1 input (B, w1i) */  \
            const uint4* Pa = (const uint4*)SRC[0][0];                         \
            const uint4* Pb = (const uint4*)SRC[0][1];                         \
            _Pragma("unroll")                                                  \
            for (int q = 0; q < 8; q++) {                                      \
                uint4 ha = Pa[q], hb = Pb[q];                                  \
                __half2 a0 = u2h2(ha.x), a1 = u2h2(ha.y),                      \
                        a2 = u2h2(ha.z), a3 = u2h2(ha.w);                      \
                __half2 e0 = u2h2(hb.x), e1 = u2h2(hb.y),                      \
                        e2 = u2h2(hb.z), e3 = u2h2(hb.w);                      \
                __half2 u0 = w0s[4*q+0][sidx], u1 = w0s[4*q+1][sidx];          \
                __half2 u2 = w0s[4*q+2][sidx], u3 = w0s[4*q+3][sidx];          \
                A0[0] = __hfma2(u0, a0, A0[0]);                                \
                A0[1] = __hfma2(u1, a1, A0[1]);                                \
                A0[2] = __hfma2(u2, a2, A0[2]);                                \
                A0[3] = __hfma2(u3, a3, A0[3]);                                \
                A1[0] = __hfma2(u0, e0, A1[0]);                                \
                A1[1] = __hfma2(u1, e1, A1[1]);                                \
                A1[2] = __hfma2(u2, e2, A1[2]);                                \
                A1[3] = __hfma2(u3, e3, A1[3]);                                \
                B0[0] = __hfma2(w1iR[4*q+0], a0, B0[0]);                       \
                B0[1] = __hfma2(w1iR[4*q+1], a1, B0[1]);                       \
                B0[2] = __hfma2(w1iR[4*q+2], a2, B0[2]);                       \
                B0[3] = __hfma2(w1iR[4*q+3], a3, B0[3]);                       \
                B1[0] = __hfma2(w1iR[4*q+0], e0, B1[0]);                       \
                B1[1] = __hfma2(w1iR[4*q+1], e1, B1[1]);                       \
                B1[2] = __hfma2(w1iR[4*q+2], e2, B1[2]);                       \
                B1[3] = __hfma2(w1iR[4*q+3], e3, B1[3]);                       \
            }                                                                  \
        }                                                                      \
        float hd0, hd1;                                                        \
        if (s_ < T_STEPS) {                                                    \
            LSTM_TAIL(DST, 0, A0, A1,                                          \
                      fmaf(wih0v, __half2float(xsh[0][s_]), bias0),            \
                      fmaf(wih0v, __half2float(xsh[1][s_]), bias0),            \
                      c00, c01, hd0, hd1)                                      \
        }                                                                      \
        {   /* Phase 2: h1 -> l1 rec (B, w1r) */                               \
            const uint4* Pa = (const uint4*)SRC[1][0];                         \
            const uint4* Pb = (const uint4*)SRC[1][1];                         \
            _Pragma("unroll")                                                  \
            for (int q = 0; q < 8; q++) {                                      \
                uint4 ha = Pa[q], hb = Pb[q];                                  \
                B0[0] = __hfma2(w1rR[4*q+0], u2h2(ha.x), B0[0]);               \
                B0[1] = __hfma2(w1rR[4*q+1], u2h2(ha.y), B0[1]);               \
                B0[2] = __hfma2(w1rR[4*q+2], u2h2(ha.z), B0[2]);               \
                B0[3] = __hfma2(w1rR[4*q+3], u2h2(ha.w), B0[3]);               \
                B1[0] = __hfma2(w1rR[4*q+0], u2h2(hb.x), B1[0]);               \
                B1[1] = __hfma2(w1rR[4*q+1], u2h2(hb.y), B1[1]);               \
                B1[2] = __hfma2(w1rR[4*q+2], u2h2(hb.z), B1[2]);               \
                B1[3] = __hfma2(w1rR[4*q+3], u2h2(hb.w), B1[3]);               \
            }                                                                  \
        }                                                                      \
        if (s_ >= 1 && s_ <= T_STEPS) {                                        \
            LSTM_TAIL(DST, 1, B0, B1, bias1, bias1, c10, c11, hd0, hd1)        \
        }                                                                      \
        BAR_ALL();                                                             \
    }

// Group B superstep: l2 (w2i over h1, w2r over h2).
#define BSTEP(SRC, DST, SVAL)                                                  \
    {                                                                          \
        const int s_ = (SVAL);                                                 \
        __half2 C0[4], C1[4];                                                  \
        _Pragma("unroll")                                                      \
        for (int i = 0; i < 4; i++) {                                          \
            C0[i] = __float2half2_rn(0.f); C1[i] = __float2half2_rn(0.f);      \
        }                                                                      \
        {                                                                      \
            const uint4* Pa = (const uint4*)SRC[1][0];                         \
            const uint4* Pb = (const uint4*)SRC[1][1];                         \
            _Pragma("unroll")                                                  \
            for (int q = 0; q < 8; q++) {                                      \
                uint4 ha = Pa[q], hb = Pb[q];                                  \
                C0[0] = __hfma2(w2iR[4*q+0], u2h2(ha.x), C0[0]);               \
                C0[1] = __hfma2(w2iR[4*q+1], u2h2(ha.y), C0[1]);               \
                C0[2] = __hfma2(w2iR[4*q+2], u2h2(ha.z), C0[2]);               \
                C0[3] = __hfma2(w2iR[4*q+3], u2h2(ha.w), C0[3]);               \
                C1[0] = __hfma2(w2iR[4*q+0], u2h2(hb.x), C1[0]);               \
                C1[1] = __hfma2(w2iR[4*q+1], u2h2(hb.y), C1[1]);               \
                C1[2] = __hfma2(w2iR[4*q+2], u2h2(hb.z), C1[2]);               \
                C1[3] = __hfma2(w2iR[4*q+3], u2h2(hb.w), C1[3]);               \
            }                                                                  \
        }                                                                      \
        {                                                                      \
            const uint4* Pa = (const uint4*)SRC[2][0];                         \
            const uint4* Pb = (const uint4*)SRC[2][1];                         \
            _Pragma("unroll")                                                  \
            for (int q = 0; q < 8; q++) {                                      \
                uint4 ha = Pa[q], hb = Pb[q];                                  \
                C0[0] = __hfma2(w2rR[4*q+0], u2h2(ha.x), C0[0]);               \
                C0[1] = __hfma2(w2rR[4*q+1], u2h2(ha.y), C0[1]);               \
                C0[2] = __hfma2(w2rR[4*q+2], u2h2(ha.z), C0[2]);               \
                C0[3] = __hfma2(w2rR[4*q+3], u2h2(ha.w), C0[3]);               \
                C1[0] = __hfma2(w2rR[4*q+0], u2h2(hb.x), C1[0]);               \
                C1[1] = __hfma2(w2rR[4*q+1], u2h2(hb.y), C1[1]);               \
                C1[2] = __hfma2(w2rR[4*q+2], u2h2(hb.z), C1[2]);               \
                C1[3] = __hfma2(w2rR[4*q+3], u2h2(hb.w), C1[3]);               \
            }                                                                  \
        }                                                                      \
        float hd0, hd1;                                                        \
        if (s_ >= 2) {                                                         \
            LSTM_TAIL(DST, 2, C0, C1, bias2, bias2, c20, c21, hd0, hd1)        \
            if (s_ == T_STEPS + 1 && type == 0) {                              \
                h2last[0][j] = hd0;                                            \
                h2last[1][j] = hd1;                                            \
            }                                                                  \
        }                                                                      \
        BAR_ALL();                                                             \
    }

__global__ void __launch_bounds__(512, 1) lstm_all(
    const float* __restrict__ x,
    const float* __restrict__ Wih0, const float* __restrict__ Whh0,
    const float* __restrict__ bih0, const float* __restrict__ bhh0,
    const float* __restrict__ Wih1, const float* __restrict__ Whh1,
    const float* __restrict__ bih1, const float* __restrict__ bhh1,
    const float* __restrict__ Wih2, const float* __restrict__ Whh2,
    const float* __restrict__ bih2, const float* __restrict__ bhh2,
    const float* __restrict__ fcW,  const float* __restrict__ fcb,
    float* __restrict__ out)
{
    __shared__ __align__(16) __half   xsh[2][T_STEPS];      // 8 KB (x as fp16)
    __shared__ __align__(16) __half2  w0s[32][GATES];       // 32 KB (Whh0, j*4+type layout)
    __shared__ __align__(16) __half2  hsA[3][2][HID / 2];   // parity A
    __shared__ __align__(16) __half2  hsB[3][2][HID / 2];   // parity B
    __shared__ __align__(16) float    h2last[2][HID];

    const int tid = threadIdx.x;
    const int b0  = blockIdx.x * 2;

    {   // stage x rows as fp16 (coalesced float4 -> 2 half2 each)
        const float4* xr = (const float4*)(x + (size_t)b0 * T_STEPS);
        __half2* xd = (__half2*)xsh;
        float4 v0 = xr[tid], v1 = xr[tid + 512];
        xd[2 * tid]             = __floats2half2_rn(v0.x, v0.y);
        xd[2 * tid + 1]         = __floats2half2_rn(v0.z, v0.w);
        xd[2 * (tid + 512)]     = __floats2half2_rn(v1.x, v1.y);
        xd[2 * (tid + 512) + 1] = __floats2half2_rn(v1.z, v1.w);
    }
    if (tid < 192) {   // zero both parity arrays (bounded reads during fill)
        ((__half2*)hsA)[tid] = __float2half2_rn(0.f);
        ((__half2*)hsB)[tid] = __float2half2_rn(0.f);
    }
    __syncthreads();

    if (tid < 256) {
        // ---------------- Group A: layers 0 + 1 ----------------
        const int w = tid >> 5, l = tid & 31;
        const int j = (w << 3) | (l >> 2);
        const int type = l & 3;
        const int gr = type * HID + j;
        const int sidx = (j << 2) | type;            // bank-conflict-free column

        const float wih0v = Wih0[gr];
        const float bias0 = bih0[gr] + bhh0[gr];
        const float bias1 = bih1[gr] + bhh1[gr];

        __half2 w1iR[32], w1rR[32];
        {
            const float2* p0 = (const float2*)(Whh0 + gr * HID);
            const float2* p1 = (const float2*)(Wih1 + gr * HID);
            const float2* p2 = (const float2*)(Whh1 + gr * HID);
#pragma unroll
            for (int q = 0; q < 32; q++) {
                w0s[q][sidx] = __float22half2_rn(p0[q]);   // own entries only
                w1iR[q] = __float22half2_rn(p1[q]);
                w1rR[q] = __float22half2_rn(p2[q]);
            }
        }
        float c00 = 0.f, c01 = 0.f, c10 = 0.f, c11 = 0.f;

#pragma unroll 1
        for (int s2 = 0; s2 < (T_STEPS + 2) / 2; s2++) {
            const int sb = s2 * 2;
            ASTEP(hsA, hsB, sb)
            ASTEP(hsB, hsA, sb + 1)
        }

        // Fused FC: out[b0+r][e] = h2last[r] . fcW[e] + fcb[e]
        {
            const int r = tid >> 7, e = tid & 127;
            const float4* w4 = (const float4*)(fcW + e * HID);
            const float4* h4 = (const float4*)(h2last[r]);
            float acc = 0.f;
#pragma unroll
            for (int q = 0; q < 16; q++) {
                float4 a = w4[q], h = h4[q];
                acc = fmaf(a.x, h.x, acc);
                acc = fmaf(a.y, h.y, acc);
                acc = fmaf(a.z, h.z, acc);
                acc = fmaf(a.w, h.w, acc);
            }
            out[(size_t)(b0 + r) * EMBED + e] = acc + fcb[e];
        }
    } else {
        // ---------------- Group B: layer 2 ----------------
        const int t2 = tid - 256;
        const int w = t2 >> 5, l = t2 & 31;
        const int j = (w << 3) | (l >> 2);
        const int type = l & 3;
        const int gr = type * HID + j;

        const float bias2 = bih2[gr] + bhh2[gr];

        __half2 w2iR[32], w2rR[32];
        {
            const float2* p3 = (const float2*)(Wih2 + gr * HID);
            const float2* p4 = (const float2*)(Whh2 + gr * HID);
#pragma unroll
            for (int q = 0; q < 32; q++) {
                w2iR[q] = __float22half2_rn(p3[q]);
                w2rR[q] = __float22half2_rn(p4[q]);
            }
        }
        float c20 = 0.f, c21 = 0.f;

#pragma unroll 1
        for (int s2 = 0; s2 < (T_STEPS + 2) / 2; s2++) {
            const int sb = s2 * 2;
            BSTEP(hsA, hsB, sb)
            BSTEP(hsB, hsA, sb + 1)
        }
    }
}

// ============================================================================
extern "C" void kernel_launch(void* const* d_in, const int* in_sizes, int n_in,
                              void* d_out, int out_size)
{
    const float* x    = (const float*)d_in[0];
    const float* Wih0 = (const float*)d_in[1];
    const float* Whh0 = (const float*)d_in[2];
    const float* bih0 = (const float*)d_in[3];
    const float* bhh0 = (const float*)d_in[4];
    const float* Wih1 = (const float*)d_in[5];
    const float* Whh1 = (const float*)d_in[6];
    const float* bih1 = (const float*)d_in[7];
    const float* bhh1 = (const float*)d_in[8];
    const float* Wih2 = (const float*)d_in[9];
    const float* Whh2 = (const float*)d_in[10];
    const float* bih2 = (const float*)d_in[11];
    const float* bhh2 = (const float*)d_in[12];
    const float* fcW  = (const float*)d_in[13];
    const float* fcb  = (const float*)d_in[14];

    lstm_all<<<BATCH / 2, 512>>>(x,
                                 Wih0, Whh0, bih0, bhh0,
                                 Wih1, Whh1, bih1, bhh1,
                                 Wih2, Whh2, bih2, bhh2,
                                 fcW, fcb, (float*)d_out);
}

// round 13
// speedup vs baseline: 1.1988x; 1.1988x over previous
#include <cuda_runtime.h>
#include <cuda_fp16.h>

#define T_STEPS 2048
#define BATCH   256
#define HID     64
#define EMBED   128

__device__ __forceinline__ float fast_tanh(float x) {
    float y;
    asm("tanh.approx.f32 %0, %1;" : "=f"(y) : "f"(x));
    return y;
}
__device__ __forceinline__ float fast_sigm(float x) {
    return fmaf(fast_tanh(0.5f * x), 0.5f, 0.5f);
}
__device__ __forceinline__ __half2 u2h2(unsigned int u) {
    return *reinterpret_cast<__half2*>(&u);
}

// Thread->gate map: warp w, lane l: unit j = w*8 + (l>>2), type = l&3
// (0:i 1:f 2:g 3:o). Weight row gr = type*64 + j (PyTorch order). Parallel
// xor-shuffles (1,2,3) deliver (i,f,g,o) to the type==0 lane which owns the
// c/h update for unit j. Non-type0 lanes compute bounded garbage (fp32 c,
// |h|<=1); never committed.
//
// Diagonal pipeline: superstep s computes l0[t=s], l1[t=s-1], l2[t=s-2].
// All reads from hs[cur] (written at superstep s-1); writes to hs[nxt];
// one barrier per superstep.
//
// Tail chain (serial, barrier-gated): HADD2-tree reduce (depth 3) ->
// MUFU.TANH nonlin -> 3 parallel xor-shuffles -> c FMA -> MUFU.TANH ->
// scalar st.shared.b16 of h (no pack shuffle).

#define LSTM_TAIL(LYR, ACC0, ACC1, IN0, IN1, Cr0, Cr1, H0OUT, H1OUT)           \
    {                                                                          \
        __half2 t01_ = __hadd2(ACC0[0], ACC0[1]);                              \
        __half2 t23_ = __hadd2(ACC0[2], ACC0[3]);                              \
        float2  tf_  = __half22float2(__hadd2(t01_, t23_));                    \
        float v0 = (IN0) + tf_.x + tf_.y;                                      \
        t01_ = __hadd2(ACC1[0], ACC1[1]);                                      \
        t23_ = __hadd2(ACC1[2], ACC1[3]);                                      \
        tf_  = __half22float2(__hadd2(t01_, t23_));                            \
        float v1 = (IN1) + tf_.x + tf_.y;                                      \
        if (type == 2) { v0 = fast_tanh(v0); v1 = fast_tanh(v1); }             \
        else           { v0 = fast_sigm(v0); v1 = fast_sigm(v1); }             \
        float f0 = __shfl_xor_sync(0xffffffffu, v0, 1);                        \
        float g0 = __shfl_xor_sync(0xffffffffu, v0, 2);                        \
        float o0 = __shfl_xor_sync(0xffffffffu, v0, 3);                        \
        float f1 = __shfl_xor_sync(0xffffffffu, v1, 1);                        \
        float g1 = __shfl_xor_sync(0xffffffffu, v1, 2);                        \
        float o1 = __shfl_xor_sync(0xffffffffu, v1, 3);                        \
        Cr0 = f0 * Cr0 + v0 * g0;                                              \
        Cr1 = f1 * Cr1 + v1 * g1;                                              \
        float h0_ = o0 * fast_tanh(Cr0);                                       \
        float h1_ = o1 * fast_tanh(Cr1);                                       \
        if (type == 0) {                                                       \
            hs[nxt][LYR][0][j] = __float2half_rn(h0_);                         \
            hs[nxt][LYR][1][j] = __float2half_rn(h1_);                         \
        }                                                                      \
        H0OUT = h0_; H1OUT = h1_;                                              \
    }

__global__ void __launch_bounds__(256, 1) lstm_all(
    const float* __restrict__ x,
    const float* __restrict__ Wih0, const float* __restrict__ Whh0,
    const float* __restrict__ bih0, const float* __restrict__ bhh0,
    const float* __restrict__ Wih1, const float* __restrict__ Whh1,
    const float* __restrict__ bih1, const float* __restrict__ bhh1,
    const float* __restrict__ Wih2, const float* __restrict__ Whh2,
    const float* __restrict__ bih2, const float* __restrict__ bhh2,
    const float* __restrict__ fcW,  const float* __restrict__ fcb,
    float* __restrict__ out)
{
    __shared__ __align__(16) float  xs[2][T_STEPS];       // 16 KB
    __shared__ __align__(16) __half hs[2][3][2][HID];     // [parity][layer][row][j]
    __shared__ __align__(16) float  h2last[2][HID];

    const int tid = threadIdx.x;
    const int b0  = blockIdx.x * 2;

    {   // stage x rows (coalesced float4)
        const float4* xr = (const float4*)(x + (size_t)b0 * T_STEPS);
        float4* xd = (float4*)xs;
#pragma unroll
        for (int i = 0; i < 4; i++) xd[tid + 256 * i] = xr[tid + 256 * i];
    }

    const int w = tid >> 5, l = tid & 31;
    const int j = (w << 3) | (l >> 2);
    const int type = l & 3;
    const int gr = type * HID + j;

    const float wih0v = Wih0[gr];
    const float bias0 = bih0[gr] + bhh0[gr];
    const float bias1 = bih1[gr] + bhh1[gr];
    const float bias2 = bih2[gr] + bhh2[gr];

    // Weights as half2 (k, k+1) pairs: 5 x 32 regs.
    __half2 w0r[32], w1i[32], w1r[32], w2i[32], w2r[32];
    {
        const float2* p0 = (const float2*)(Whh0 + gr * HID);
        const float2* p1 = (const float2*)(Wih1 + gr * HID);
        const float2* p2 = (const float2*)(Whh1 + gr * HID);
        const float2* p3 = (const float2*)(Wih2 + gr * HID);
        const float2* p4 = (const float2*)(Whh2 + gr * HID);
#pragma unroll
        for (int q = 0; q < 32; q++) {
            w0r[q] = __float22half2_rn(p0[q]);
            w1i[q] = __float22half2_rn(p1[q]);
            w1r[q] = __float22half2_rn(p2[q]);
            w2i[q] = __float22half2_rn(p3[q]);
            w2r[q] = __float22half2_rn(p4[q]);
        }
    }

    // Zero both parities of all layer states (bounded reads during fill).
    {
        __half2* hp = (__half2*)hs;
        for (int i = tid; i < 2 * 3 * 2 * (HID / 2); i += 256)
            hp[i] = __float2half2_rn(0.f);
    }
    float c00 = 0.f, c01 = 0.f, c10 = 0.f, c11 = 0.f, c20 = 0.f, c21 = 0.f;
    __syncthreads();

    for (int s = 0; s < T_STEPS + 2; s++) {
        const int cur = s & 1, nxt = cur ^ 1;

        __half2 A0[4], A1[4], B0[4], B1[4], C0[4], C1[4];
#pragma unroll
        for (int i = 0; i < 4; i++) {
            A0[i] = __float2half2_rn(0.f); A1[i] = __float2half2_rn(0.f);
            B0[i] = __float2half2_rn(0.f); B1[i] = __float2half2_rn(0.f);
            C0[i] = __float2half2_rn(0.f); C1[i] = __float2half2_rn(0.f);
        }

        const uint4* P00 = (const uint4*)hs[cur][0][0];
        const uint4* P01 = (const uint4*)hs[cur][0][1];
        const uint4* P10 = (const uint4*)hs[cur][1][0];
        const uint4* P11 = (const uint4*)hs[cur][1][1];
        const uint4* P20 = (const uint4*)hs[cur][2][0];
        const uint4* P21 = (const uint4*)hs[cur][2][1];

        // Phase 1: h0[cur] feeds l0 rec (A) and l1 input (B).
#pragma unroll
        for (int q = 0; q < 8; q++) {
            uint4 ha = P00[q], hb = P01[q];
            __half2 a0 = u2h2(ha.x), a1 = u2h2(ha.y), a2 = u2h2(ha.z), a3 = u2h2(ha.w);
            __half2 e0 = u2h2(hb.x), e1 = u2h2(hb.y), e2 = u2h2(hb.z), e3 = u2h2(hb.w);
            A0[0] = __hfma2(w0r[4*q+0], a0, A0[0]);
            A0[1] = __hfma2(w0r[4*q+1], a1, A0[1]);
            A0[2] = __hfma2(w0r[4*q+2], a2, A0[2]);
            A0[3] = __hfma2(w0r[4*q+3], a3, A0[3]);
            A1[0] = __hfma2(w0r[4*q+0], e0, A1[0]);
            A1[1] = __hfma2(w0r[4*q+1], e1, A1[1]);
            A1[2] = __hfma2(w0r[4*q+2], e2, A1[2]);
            A1[3] = __hfma2(w0r[4*q+3], e3, A1[3]);
            B0[0] = __hfma2(w1i[4*q+0], a0, B0[0]);
            B0[1] = __hfma2(w1i[4*q+1], a1, B0[1]);
            B0[2] = __hfma2(w1i[4*q+2], a2, B0[2]);
            B0[3] = __hfma2(w1i[4*q+3], a3, B0[3]);
            B1[0] = __hfma2(w1i[4*q+0], e0, B1[0]);
            B1[1] = __hfma2(w1i[4*q+1], e1, B1[1]);
            B1[2] = __hfma2(w1i[4*q+2], e2, B1[2]);
            B1[3] = __hfma2(w1i[4*q+3], e3, B1[3]);
        }
        // Phase 2: h1[cur] feeds l1 rec (B) and l2 input (C).
#pragma unroll
        for (int q = 0; q < 8; q++) {
            uint4 ha = P10[q], hb = P11[q];
            __half2 a0 = u2h2(ha.x), a1 = u2h2(ha.y), a2 = u2h2(ha.z), a3 = u2h2(ha.w);
            __half2 e0 = u2h2(hb.x), e1 = u2h2(hb.y), e2 = u2h2(hb.z), e3 = u2h2(hb.w);
            B0[0] = __hfma2(w1r[4*q+0], a0, B0[0]);
            B0[1] = __hfma2(w1r[4*q+1], a1, B0[1]);
            B0[2] = __hfma2(w1r[4*q+2], a2, B0[2]);
            B0[3] = __hfma2(w1r[4*q+3], a3, B0[3]);
            B1[0] = __hfma2(w1r[4*q+0], e0, B1[0]);
            B1[1] = __hfma2(w1r[4*q+1], e1, B1[1]);
            B1[2] = __hfma2(w1r[4*q+2], e2, B1[2]);
            B1[3] = __hfma2(w1r[4*q+3], e3, B1[3]);
            C0[0] = __hfma2(w2i[4*q+0], a0, C0[0]);
            C0[1] = __hfma2(w2i[4*q+1], a1, C0[1]);
            C0[2] = __hfma2(w2i[4*q+2], a2, C0[2]);
            C0[3] = __hfma2(w2i[4*q+3], a3, C0[3]);
            C1[0] = __hfma2(w2i[4*q+0], e0, C1[0]);
            C1[1] = __hfma2(w2i[4*q+1], e1, C1[1]);
            C1[2] = __hfma2(w2i[4*q+2], e2, C1[2]);
            C1[3] = __hfma2(w2i[4*q+3], e3, C1[3]);
        }
        // Phase 3: h2[cur] feeds l2 rec (C).
#pragma unroll
        for (int q = 0; q < 8; q++) {
            uint4 ha = P20[q], hb = P21[q];
            C0[0] = __hfma2(w2r[4*q+0], u2h2(ha.x), C0[0]);
            C0[1] = __hfma2(w2r[4*q+1], u2h2(ha.y), C0[1]);
            C0[2] = __hfma2(w2r[4*q+2], u2h2(ha.z), C0[2]);
            C0[3] = __hfma2(w2r[4*q+3], u2h2(ha.w), C0[3]);
            C1[0] = __hfma2(w2r[4*q+0], u2h2(hb.x), C1[0]);
            C1[1] = __hfma2(w2r[4*q+1], u2h2(hb.y), C1[1]);
            C1[2] = __hfma2(w2r[4*q+2], u2h2(hb.z), C1[2]);
            C1[3] = __hfma2(w2r[4*q+3], u2h2(hb.w), C1[3]);
        }

        float hd0, hd1;   // tail h outputs (only l2's final values used)

        if (s < T_STEPS) {        // layer 0, t = s
            LSTM_TAIL(0, A0, A1,
                      fmaf(wih0v, xs[0][s], bias0),
                      fmaf(wih0v, xs[1][s], bias0),
                      c00, c01, hd0, hd1)
        }
        if (s >= 1 && s <= T_STEPS) {   // layer 1, t = s-1
            LSTM_TAIL(1, B0, B1, bias1, bias1, c10, c11, hd0, hd1)
        }
        if (s >= 2) {                    // layer 2, t = s-2
            LSTM_TAIL(2, C0, C1, bias2, bias2, c20, c21, hd0, hd1)
            if (s == T_STEPS + 1 && type == 0) {
                h2last[0][j] = hd0;
                h2last[1][j] = hd1;
            }
        }
        __syncthreads();
    }

    // Fused FC: out[b0+r][e] = h2last[r] . fcW[e] + fcb[e]
    {
        const int r = tid >> 7, e = tid & 127;
        const float4* w4 = (const float4*)(fcW + e * HID);
        const float4* h4 = (const float4*)(h2last[r]);
        float acc = 0.f;
#pragma unroll
        for (int q = 0; q < 16; q++) {
            float4 a = w4[q], h = h4[q];
            acc = fmaf(a.x, h.x, acc);
            acc = fmaf(a.y, h.y, acc);
            acc = fmaf(a.z, h.z, acc);
            acc = fmaf(a.w, h.w, acc);
        }
        out[(size_t)(b0 + r) * EMBED + e] = acc + fcb[e];
    }
}

// ============================================================================
extern "C" void kernel_launch(void* const* d_in, const int* in_sizes, int n_in,
                              void* d_out, int out_size)
{
    const float* x    = (const float*)d_in[0];
    const float* Wih0 = (const float*)d_in[1];
    const float* Whh0 = (const float*)d_in[2];
    const float* bih0 = (const float*)d_in[3];
    const float* bhh0 = (const float*)d_in[4];
    const float* Wih1 = (const float*)d_in[5];
    const float* Whh1 = (const float*)d_in[6];
    const float* bih1 = (const float*)d_in[7];
    const float* bhh1 = (const float*)d_in[8];
    const float* Wih2 = (const float*)d_in[9];
    const float* Whh2 = (const float*)d_in[10];
    const float* bih2 = (const float*)d_in[11];
    const float* bhh2 = (const float*)d_in[12];
    const float* fcW  = (const float*)d_in[13];
    const float* fcb  = (const float*)d_in[14];

    lstm_all<<<BATCH / 2, 256>>>(x,
                                 Wih0, Whh0, bih0, bhh0,
                                 Wih1, Whh1, bih1, bhh1,
                                 Wih2, Whh2, bih2, bhh2,
                                 fcW, fcb, (float*)d_out);
}